// round 2
// baseline (speedup 1.0000x reference)
#include <cuda_runtime.h>
#include <math.h>

#define HH 7   // heads per state (Fano plane points)
#define DD 8   // octonion dim

__device__ double g_qerr_sum;
__device__ double g_fano_sum;

__global__ void zero_accums_k() {
    g_qerr_sum = 0.0;
    g_fano_sum = 0.0;
}

__inline__ __device__ double blockReduceSumD(double val) {
    __shared__ double sh[32];
    int lane = threadIdx.x & 31;
    int wid  = threadIdx.x >> 5;
    #pragma unroll
    for (int o = 16; o > 0; o >>= 1)
        val += __shfl_down_sync(0xffffffffu, val, o);
    if (lane == 0) sh[wid] = val;
    __syncthreads();
    int nw = blockDim.x >> 5;
    val = (threadIdx.x < nw) ? sh[lane] : 0.0;
    if (wid == 0) {
        #pragma unroll
        for (int o = 16; o > 0; o >>= 1)
            val += __shfl_down_sync(0xffffffffu, val, o);
    }
    return val;
}

// Closed-form nearest E8 root (all roots have |r|^2 = 2, so nearest = argmax dot).
// Returns index into the canonical 240-root list; writes root vector to root_out.
__device__ __forceinline__ int e8_nearest(const float r[8], float root_out[8]) {
    float a[8];
    bool  neg[8];
    #pragma unroll
    for (int k = 0; k < 8; k++) {
        neg[k] = r[k] < 0.0f;
        a[k]   = fabsf(r[k]);
    }
    // top-2 of |r| (first-index wins ties, matching argmin-first)
    int i1 = 0; float a1 = a[0];
    #pragma unroll
    for (int k = 1; k < 8; k++) if (a[k] > a1) { a1 = a[k]; i1 = k; }
    int i2 = -1; float a2 = -1.0f;
    #pragma unroll
    for (int k = 0; k < 8; k++) if (k != i1 && a[k] > a2) { a2 = a[k]; i2 = k; }
    float pairDot = a1 + a2;

    float s = 0.0f, amin = a[0]; int imin = 0;
    #pragma unroll
    for (int k = 0; k < 8; k++) {
        s += a[k];
        if (a[k] < amin) { amin = a[k]; imin = k; }
    }
    int par = 0;
    #pragma unroll
    for (int k = 0; k < 8; k++) par ^= (neg[k] ? 1 : 0);
    float halfDot = 0.5f * (par ? (s - 2.0f * amin) : s);

    if (pairDot >= halfDot) {
        // pair root +-e_i +- e_j, ordering: i<j, si in (+,-), sj in (+,-)
        int i = (i1 < i2) ? i1 : i2;
        int j = (i1 < i2) ? i2 : i1;
        #pragma unroll
        for (int k = 0; k < 8; k++) root_out[k] = 0.0f;
        root_out[i] = neg[i] ? -1.0f : 1.0f;
        root_out[j] = neg[j] ? -1.0f : 1.0f;
        int pidx = i * 7 - (i * (i - 1)) / 2 + (j - i - 1);
        return 4 * pidx + (neg[i] ? 2 : 0) + (neg[j] ? 1 : 0);
    } else {
        // half root (+-1/2)^8 with even # of minus signs; flip min-|x| comp if parity odd
        bool nn[8];
        #pragma unroll
        for (int k = 0; k < 8; k++) nn[k] = neg[k];
        if (par) nn[imin] = !nn[imin];
        int v = 0;
        #pragma unroll
        for (int k = 0; k < 8; k++) {
            root_out[k] = nn[k] ? -0.5f : 0.5f;
            v |= (nn[k] ? 1 : 0) << (7 - k);
        }
        return 112 + (v >> 1);  // rank among even-parity bytes = upper 7 bits
    }
}

__global__ void quantize_kernel(const float* __restrict__ states,
                                float* __restrict__ out,
                                int nrows, size_t off_idx) {
    int row = blockIdx.x * blockDim.x + threadIdx.x;
    double qe = 0.0;
    if (row < nrows) {
        float x[8];
        const float4* p = reinterpret_cast<const float4*>(states + (size_t)row * 8);
        float4 v0 = p[0], v1 = p[1];
        x[0] = v0.x; x[1] = v0.y; x[2] = v0.z; x[3] = v0.w;
        x[4] = v1.x; x[5] = v1.y; x[6] = v1.z; x[7] = v1.w;

        float qsum[8], res[8], root[8];
        #pragma unroll
        for (int k = 0; k < 8; k++) { qsum[k] = 0.0f; res[k] = x[k]; }

        int idx0 = e8_nearest(res, root);
        #pragma unroll
        for (int k = 0; k < 8; k++) { qsum[k] += root[k]; res[k] = x[k] - qsum[k]; }

        int idx1 = e8_nearest(res, root);
        #pragma unroll
        for (int k = 0; k < 8; k++) qsum[k] += root[k];

        float4 q0, q1;
        q0.x = qsum[0]; q0.y = qsum[1]; q0.z = qsum[2]; q0.w = qsum[3];
        q1.x = qsum[4]; q1.y = qsum[5]; q1.z = qsum[6]; q1.w = qsum[7];
        float4* po = reinterpret_cast<float4*>(out + (size_t)row * 8);
        po[0] = q0; po[1] = q1;

        out[off_idx + row]                 = (float)idx0;
        out[off_idx + (size_t)nrows + row] = (float)idx1;

        #pragma unroll
        for (int k = 0; k < 8; k++) {
            float d = x[k] - qsum[k];
            qe += (double)(d * d);
        }
    }
    double bs = blockReduceSumD(qe);
    if (threadIdx.x == 0) atomicAdd(&g_qerr_sum, bs);
}

__device__ __forceinline__ void qmul(const float q[4], const float p[4], float o[4]) {
    o[0] = q[0]*p[0] - q[1]*p[1] - q[2]*p[2] - q[3]*p[3];
    o[1] = q[0]*p[1] + q[1]*p[0] + q[2]*p[3] - q[3]*p[2];
    o[2] = q[0]*p[2] - q[1]*p[3] + q[2]*p[0] + q[3]*p[1];
    o[3] = q[0]*p[3] + q[1]*p[2] - q[2]*p[1] + q[3]*p[0];
}

__device__ __forceinline__ void load8(const float* __restrict__ q, size_t row, float v[8]) {
    const float4* p = reinterpret_cast<const float4*>(q + row * 8);
    float4 a = p[0], b = p[1];
    v[0]=a.x; v[1]=a.y; v[2]=a.z; v[3]=a.w;
    v[4]=b.x; v[5]=b.y; v[6]=b.z; v[7]=b.w;
}

__global__ void fano_kernel(const float* __restrict__ q,
                            const int* __restrict__ li,
                            const int* __restrict__ lj,
                            const int* __restrict__ lk,
                            float* __restrict__ prod_out,
                            float* __restrict__ align_out,
                            int B, int L) {
    int t = blockIdx.x * blockDim.x + threadIdx.x;
    double fs = 0.0;
    if (t < B * L) {
        int b = t / L;
        int l = t - b * L;
        float av[8], bv[8], cv[8];
        load8(q, (size_t)b * HH + li[l], av);
        load8(q, (size_t)b * HH + lj[l], bv);
        load8(q, (size_t)b * HH + lk[l], cv);

        float aq[4] = {av[0], av[1], av[2], av[3]};
        float bq[4] = {av[4], av[5], av[6], av[7]};
        float cq[4] = {bv[0], bv[1], bv[2], bv[3]};
        float dq[4] = {bv[4], bv[5], bv[6], bv[7]};
        float dconj[4] = {dq[0], -dq[1], -dq[2], -dq[3]};
        float cconj[4] = {cq[0], -cq[1], -cq[2], -cq[3]};

        float t1[4], t2[4], t3[4], t4[4], pr[8];
        qmul(aq, cq, t1);
        qmul(dconj, bq, t2);
        qmul(dq, aq, t3);
        qmul(bq, cconj, t4);
        #pragma unroll
        for (int k = 0; k < 4; k++) {
            pr[k]     = t1[k] - t2[k];
            pr[4 + k] = t3[k] + t4[k];
        }

        float dot = 0.0f, np2 = 0.0f, nc2 = 0.0f;
        #pragma unroll
        for (int k = 0; k < 8; k++) {
            dot += pr[k] * cv[k];
            np2 += pr[k] * pr[k];
            nc2 += cv[k] * cv[k];
        }
        float denom = fmaxf(sqrtf(np2) * sqrtf(nc2), 1e-8f);
        float align = dot / denom;

        // products region starts at an odd float offset (q_err scalar precedes it)
        // -> only 4-byte aligned; must use scalar stores.
        float* po = prod_out + (size_t)t * 8;
        #pragma unroll
        for (int k = 0; k < 8; k++) po[k] = pr[k];
        align_out[t] = align;

        float ac = fminf(fmaxf(align, -1.0f), 1.0f);
        fs = (double)(1.0f - ac);
    }
    double bs = blockReduceSumD(fs);
    if (threadIdx.x == 0) atomicAdd(&g_fano_sum, bs);
}

__global__ void finalize_k(float* __restrict__ qerr_out,
                           float* __restrict__ fano_out,
                           double n_q, double n_f) {
    double qe = g_qerr_sum / n_q;
    double fl = (g_fano_sum / n_f) * 0.5;
    if (fl < 0.0) fl = 0.0;
    if (fl > 1.0) fl = 1.0;
    *qerr_out = (float)qe;
    *fano_out = (float)fl;
}

extern "C" void kernel_launch(void* const* d_in, const int* in_sizes, int n_in,
                              void* d_out, int out_size) {
    const float* states = (const float*)d_in[0];
    // d_in[1] = roots (structure known analytically; not needed)
    const int* li = (const int*)d_in[2];
    const int* lj = (const int*)d_in[3];
    const int* lk = (const int*)d_in[4];

    int L = in_sizes[2];                 // 7 Fano lines
    int B = in_sizes[0] / (HH * DD);     // 65536
    int nrows = B * HH;

    float* out = (float*)d_out;
    size_t off_idx   = (size_t)nrows * 8;                 // quantized_ste
    size_t off_qerr  = off_idx + 2 * (size_t)nrows;       // indices (2, B, H)
    size_t off_prod  = off_qerr + 1;                      // q_err scalar
    size_t off_align = off_prod + (size_t)B * L * 8;      // products (B, L, 8)
    size_t off_fano  = off_align + (size_t)B * L;         // alignments (B, L)

    zero_accums_k<<<1, 1>>>();
    quantize_kernel<<<(nrows + 255) / 256, 256>>>(states, out, nrows, off_idx);
    fano_kernel<<<((B * L) + 255) / 256, 256>>>(out, li, lj, lk,
                                                out + off_prod, out + off_align, B, L);
    finalize_k<<<1, 1>>>(out + off_qerr, out + off_fano,
                         (double)nrows * 8.0, (double)B * (double)L);
}

// round 3
// speedup vs baseline: 1.2901x; 1.2901x over previous
#include <cuda_runtime.h>
#include <math.h>

#define HH 7   // heads per state (Fano plane points)
#define LL 7   // Fano lines (compile-time for fast div)

__device__ double g_qerr_sum = 0.0;
__device__ double g_fano_sum = 0.0;
__device__ unsigned g_q_count = 0;
__device__ unsigned g_f_count = 0;

__inline__ __device__ double blockReduceSumD(double val) {
    __shared__ double sh[32];
    int lane = threadIdx.x & 31;
    int wid  = threadIdx.x >> 5;
    #pragma unroll
    for (int o = 16; o > 0; o >>= 1)
        val += __shfl_down_sync(0xffffffffu, val, o);
    if (lane == 0) sh[wid] = val;
    __syncthreads();
    int nw = blockDim.x >> 5;
    val = (threadIdx.x < nw) ? sh[lane] : 0.0;
    if (wid == 0) {
        #pragma unroll
        for (int o = 16; o > 0; o >>= 1)
            val += __shfl_down_sync(0xffffffffu, val, o);
    }
    return val;
}

// Branchless closed-form nearest E8 root. All 240 roots have |r|^2=2, so
// nearest = argmax<residual,root>, computed analytically from root structure.
__device__ __forceinline__ int e8_nearest(const float r[8], float root_out[8]) {
    float a[8];
    unsigned smask = 0;   // sign bits, bit k
    unsigned rmask = 0;   // sign bits, bit (7-k)  (root-list enumeration order)
    #pragma unroll
    for (int k = 0; k < 8; k++) {
        unsigned sb = __float_as_uint(r[k]) >> 31;
        smask |= sb << k;
        rmask |= sb << (7 - k);
        a[k] = fabsf(r[k]);
    }

    // --- max (tree) + first index achieving it ---
    float m01 = fmaxf(a[0], a[1]), m23 = fmaxf(a[2], a[3]);
    float m45 = fmaxf(a[4], a[5]), m67 = fmaxf(a[6], a[7]);
    float a1 = fmaxf(fmaxf(m01, m23), fmaxf(m45, m67));
    unsigned em = 0;
    #pragma unroll
    for (int k = 0; k < 8; k++) em |= (a[k] == a1) ? (1u << k) : 0u;
    int i1 = __ffs(em) - 1;

    // --- second max: exclude i1 (a[] >= 0, so -1 acts as -inf) ---
    float b0 = (i1 == 0) ? -1.0f : a[0], b1 = (i1 == 1) ? -1.0f : a[1];
    float b2 = (i1 == 2) ? -1.0f : a[2], b3 = (i1 == 3) ? -1.0f : a[3];
    float b4 = (i1 == 4) ? -1.0f : a[4], b5 = (i1 == 5) ? -1.0f : a[5];
    float b6 = (i1 == 6) ? -1.0f : a[6], b7 = (i1 == 7) ? -1.0f : a[7];
    float a2 = fmaxf(fmaxf(fmaxf(b0, b1), fmaxf(b2, b3)),
                     fmaxf(fmaxf(b4, b5), fmaxf(b6, b7)));
    unsigned em2 = 0;
    em2 |= (b0 == a2) ? 1u : 0u;        em2 |= (b1 == a2) ? 2u : 0u;
    em2 |= (b2 == a2) ? 4u : 0u;        em2 |= (b3 == a2) ? 8u : 0u;
    em2 |= (b4 == a2) ? 16u : 0u;       em2 |= (b5 == a2) ? 32u : 0u;
    em2 |= (b6 == a2) ? 64u : 0u;       em2 |= (b7 == a2) ? 128u : 0u;
    int i2 = __ffs(em2) - 1;

    // --- sum, min + first index achieving it, parity ---
    float s = ((a[0] + a[1]) + (a[2] + a[3])) + ((a[4] + a[5]) + (a[6] + a[7]));
    float n01 = fminf(a[0], a[1]), n23 = fminf(a[2], a[3]);
    float n45 = fminf(a[4], a[5]), n67 = fminf(a[6], a[7]);
    float amin = fminf(fminf(n01, n23), fminf(n45, n67));
    unsigned nm = 0;
    #pragma unroll
    for (int k = 0; k < 8; k++) nm |= (a[k] == amin) ? (1u << k) : 0u;
    int imin = __ffs(nm) - 1;

    unsigned par = __popc(smask) & 1u;

    float pairDot = a1 + a2;
    float halfDot = 0.5f * s - (par ? amin : 0.0f);
    bool usePair = pairDot >= halfDot;

    // --- pair index: i<j among {i1,i2}; sign bits from smask ---
    int i = min(i1, i2), j = max(i1, i2);
    int pidx = i * 7 - ((i * (i - 1)) >> 1) + (j - i - 1);
    unsigned si = (smask >> i) & 1u, sj = (smask >> j) & 1u;
    int idxPair = 4 * pidx + 2 * (int)si + (int)sj;

    // --- half index: flip sign of min component if parity odd ---
    unsigned hv = rmask ^ (par << (7 - imin));
    int idxHalf = 112 + (int)(hv >> 1);

    #pragma unroll
    for (int k = 0; k < 8; k++) {
        float sgn = ((smask >> k) & 1u) ? -1.0f : 1.0f;
        float pairRoot = ((k == i1) | (k == i2)) ? sgn : 0.0f;
        float halfRoot = ((hv >> (7 - k)) & 1u) ? -0.5f : 0.5f;
        root_out[k] = usePair ? pairRoot : halfRoot;
    }
    return usePair ? idxPair : idxHalf;
}

__global__ void quantize_kernel(const float* __restrict__ states,
                                float* __restrict__ out,
                                float* __restrict__ qerr_out,
                                int nrows, size_t off_idx, double inv_nq) {
    int row = blockIdx.x * blockDim.x + threadIdx.x;
    double qe = 0.0;
    if (row < nrows) {
        float x[8];
        const float4* p = reinterpret_cast<const float4*>(states + (size_t)row * 8);
        float4 v0 = p[0], v1 = p[1];
        x[0] = v0.x; x[1] = v0.y; x[2] = v0.z; x[3] = v0.w;
        x[4] = v1.x; x[5] = v1.y; x[6] = v1.z; x[7] = v1.w;

        float res[8], root[8], qsum[8];
        #pragma unroll
        for (int k = 0; k < 8; k++) res[k] = x[k];

        int idx0 = e8_nearest(res, root);
        #pragma unroll
        for (int k = 0; k < 8; k++) { qsum[k] = root[k]; res[k] = x[k] - qsum[k]; }

        int idx1 = e8_nearest(res, root);
        float qef = 0.0f;
        #pragma unroll
        for (int k = 0; k < 8; k++) {
            qsum[k] += root[k];
            float d = x[k] - qsum[k];
            qef += d * d;
        }
        qe = (double)qef;

        float4 q0, q1;
        q0.x = qsum[0]; q0.y = qsum[1]; q0.z = qsum[2]; q0.w = qsum[3];
        q1.x = qsum[4]; q1.y = qsum[5]; q1.z = qsum[6]; q1.w = qsum[7];
        float4* po = reinterpret_cast<float4*>(out + (size_t)row * 8);
        po[0] = q0; po[1] = q1;

        out[off_idx + row]                 = (float)idx0;
        out[off_idx + (size_t)nrows + row] = (float)idx1;
    }
    double bs = blockReduceSumD(qe);
    __shared__ bool amLast;
    if (threadIdx.x == 0) {
        atomicAdd(&g_qerr_sum, bs);
        __threadfence();
        unsigned done = atomicAdd(&g_q_count, 1u);
        amLast = (done == gridDim.x - 1);
    }
    __syncthreads();
    if (amLast && threadIdx.x == 0) {
        double total = *((volatile double*)&g_qerr_sum);
        *qerr_out = (float)(total * inv_nq);
        g_qerr_sum = 0.0;
        g_q_count = 0;
    }
}

__device__ __forceinline__ void qmul(const float q[4], const float p[4], float o[4]) {
    o[0] = q[0]*p[0] - q[1]*p[1] - q[2]*p[2] - q[3]*p[3];
    o[1] = q[0]*p[1] + q[1]*p[0] + q[2]*p[3] - q[3]*p[2];
    o[2] = q[0]*p[2] - q[1]*p[3] + q[2]*p[0] + q[3]*p[1];
    o[3] = q[0]*p[3] + q[1]*p[2] - q[2]*p[1] + q[3]*p[0];
}

__device__ __forceinline__ void load8(const float* __restrict__ q, size_t row, float v[8]) {
    const float4* p = reinterpret_cast<const float4*>(q + row * 8);
    float4 a = p[0], b = p[1];
    v[0]=a.x; v[1]=a.y; v[2]=a.z; v[3]=a.w;
    v[4]=b.x; v[5]=b.y; v[6]=b.z; v[7]=b.w;
}

__global__ void fano_kernel(const float* __restrict__ q,
                            const int* __restrict__ li,
                            const int* __restrict__ lj,
                            const int* __restrict__ lk,
                            float* __restrict__ prod_out,
                            float* __restrict__ align_out,
                            float* __restrict__ fano_out,
                            int B, double inv_nf) {
    int t = blockIdx.x * blockDim.x + threadIdx.x;
    double fs = 0.0;
    if (t < B * LL) {
        int b = t / LL;              // compile-time 7 -> magic-number division
        int l = t - b * LL;
        float av[8], bv[8], cv[8];
        load8(q, (size_t)b * HH + __ldg(li + l), av);
        load8(q, (size_t)b * HH + __ldg(lj + l), bv);
        load8(q, (size_t)b * HH + __ldg(lk + l), cv);

        float aq[4] = {av[0], av[1], av[2], av[3]};
        float bq[4] = {av[4], av[5], av[6], av[7]};
        float cq[4] = {bv[0], bv[1], bv[2], bv[3]};
        float dq[4] = {bv[4], bv[5], bv[6], bv[7]};
        float dconj[4] = {dq[0], -dq[1], -dq[2], -dq[3]};
        float cconj[4] = {cq[0], -cq[1], -cq[2], -cq[3]};

        float t1[4], t2[4], t3[4], t4[4], pr[8];
        qmul(aq, cq, t1);
        qmul(dconj, bq, t2);
        qmul(dq, aq, t3);
        qmul(bq, cconj, t4);
        #pragma unroll
        for (int k = 0; k < 4; k++) {
            pr[k]     = t1[k] - t2[k];
            pr[4 + k] = t3[k] + t4[k];
        }

        float dot = 0.0f, np2 = 0.0f, nc2 = 0.0f;
        #pragma unroll
        for (int k = 0; k < 8; k++) {
            dot += pr[k] * cv[k];
            np2 += pr[k] * pr[k];
            nc2 += cv[k] * cv[k];
        }
        float denom = fmaxf(sqrtf(np2) * sqrtf(nc2), 1e-8f);
        float align = dot / denom;

        // products region starts at odd float offset -> scalar (coalesced) stores.
        float* po = prod_out + (size_t)t * 8;
        #pragma unroll
        for (int k = 0; k < 8; k++) po[k] = pr[k];
        align_out[t] = align;

        float ac = fminf(fmaxf(align, -1.0f), 1.0f);
        fs = (double)(1.0f - ac);
    }
    double bs = blockReduceSumD(fs);
    __shared__ bool amLast;
    if (threadIdx.x == 0) {
        atomicAdd(&g_fano_sum, bs);
        __threadfence();
        unsigned done = atomicAdd(&g_f_count, 1u);
        amLast = (done == gridDim.x - 1);
    }
    __syncthreads();
    if (amLast && threadIdx.x == 0) {
        double total = *((volatile double*)&g_fano_sum);
        double fl = total * inv_nf * 0.5;
        if (fl < 0.0) fl = 0.0;
        if (fl > 1.0) fl = 1.0;
        *fano_out = (float)fl;
        g_fano_sum = 0.0;
        g_f_count = 0;
    }
}

extern "C" void kernel_launch(void* const* d_in, const int* in_sizes, int n_in,
                              void* d_out, int out_size) {
    const float* states = (const float*)d_in[0];
    // d_in[1] = roots (structure known analytically; not needed)
    const int* li = (const int*)d_in[2];
    const int* lj = (const int*)d_in[3];
    const int* lk = (const int*)d_in[4];

    int B = in_sizes[0] / (HH * 8);      // 65536
    int nrows = B * HH;

    float* out = (float*)d_out;
    size_t off_idx   = (size_t)nrows * 8;                 // quantized_ste
    size_t off_qerr  = off_idx + 2 * (size_t)nrows;       // indices (2, B, H)
    size_t off_prod  = off_qerr + 1;                      // q_err scalar
    size_t off_align = off_prod + (size_t)B * LL * 8;     // products (B, L, 8)
    size_t off_fano  = off_align + (size_t)B * LL;        // alignments (B, L)

    int blocks_q = (nrows + 255) / 256;
    int blocks_f = (B * LL + 255) / 256;

    quantize_kernel<<<blocks_q, 256>>>(states, out, out + off_qerr,
                                       nrows, off_idx,
                                       1.0 / ((double)nrows * 8.0));
    fano_kernel<<<blocks_f, 256>>>(out, li, lj, lk,
                                   out + off_prod, out + off_align, out + off_fano,
                                   B, 1.0 / ((double)B * (double)LL));
}

// round 4
// speedup vs baseline: 1.5582x; 1.2078x over previous
#include <cuda_runtime.h>
#include <math.h>

#define HH 7           // heads per state (Fano plane points)
#define LL 7           // Fano lines
#define BPB 32         // states (b) per block
#define TPB (BPB * 7)  // 224 threads: 1 per row in phase 1, 1 per (b,line) in phase 2
#define SQ_STRIDE 57   // 7*8 floats per state, +1 pad (odd stride -> conflict-free)

__device__ double g_qerr_sum = 0.0;
__device__ double g_fano_sum = 0.0;
__device__ unsigned g_count = 0;

__inline__ __device__ double blockReduceSumD(double val) {
    __shared__ double sh[32];
    int lane = threadIdx.x & 31;
    int wid  = threadIdx.x >> 5;
    #pragma unroll
    for (int o = 16; o > 0; o >>= 1)
        val += __shfl_down_sync(0xffffffffu, val, o);
    if (lane == 0) sh[wid] = val;
    __syncthreads();
    int nw = (blockDim.x + 31) >> 5;
    val = (threadIdx.x < nw) ? sh[lane] : 0.0;
    if (wid == 0) {
        #pragma unroll
        for (int o = 16; o > 0; o >>= 1)
            val += __shfl_down_sync(0xffffffffu, val, o);
    }
    return val;
}

// Branchless closed-form nearest E8 root. All 240 roots have |r|^2=2, so
// nearest = argmax<residual,root>, computed analytically from root structure.
__device__ __forceinline__ int e8_nearest(const float r[8], float root_out[8]) {
    float a[8];
    unsigned smask = 0;   // sign bits, bit k
    unsigned rmask = 0;   // sign bits, bit (7-k)  (root-list enumeration order)
    #pragma unroll
    for (int k = 0; k < 8; k++) {
        unsigned sb = __float_as_uint(r[k]) >> 31;
        smask |= sb << k;
        rmask |= sb << (7 - k);
        a[k] = fabsf(r[k]);
    }

    // --- max (tree) + first index achieving it ---
    float m01 = fmaxf(a[0], a[1]), m23 = fmaxf(a[2], a[3]);
    float m45 = fmaxf(a[4], a[5]), m67 = fmaxf(a[6], a[7]);
    float a1 = fmaxf(fmaxf(m01, m23), fmaxf(m45, m67));
    unsigned em = 0;
    #pragma unroll
    for (int k = 0; k < 8; k++) em |= (a[k] == a1) ? (1u << k) : 0u;
    int i1 = __ffs(em) - 1;

    // --- second max: exclude i1 (a[] >= 0, so -1 acts as -inf) ---
    float b0 = (i1 == 0) ? -1.0f : a[0], b1 = (i1 == 1) ? -1.0f : a[1];
    float b2 = (i1 == 2) ? -1.0f : a[2], b3 = (i1 == 3) ? -1.0f : a[3];
    float b4 = (i1 == 4) ? -1.0f : a[4], b5 = (i1 == 5) ? -1.0f : a[5];
    float b6 = (i1 == 6) ? -1.0f : a[6], b7 = (i1 == 7) ? -1.0f : a[7];
    float a2 = fmaxf(fmaxf(fmaxf(b0, b1), fmaxf(b2, b3)),
                     fmaxf(fmaxf(b4, b5), fmaxf(b6, b7)));
    unsigned em2 = 0;
    em2 |= (b0 == a2) ? 1u : 0u;        em2 |= (b1 == a2) ? 2u : 0u;
    em2 |= (b2 == a2) ? 4u : 0u;        em2 |= (b3 == a2) ? 8u : 0u;
    em2 |= (b4 == a2) ? 16u : 0u;       em2 |= (b5 == a2) ? 32u : 0u;
    em2 |= (b6 == a2) ? 64u : 0u;       em2 |= (b7 == a2) ? 128u : 0u;
    int i2 = __ffs(em2) - 1;

    // --- sum, min + first index achieving it, parity ---
    float s = ((a[0] + a[1]) + (a[2] + a[3])) + ((a[4] + a[5]) + (a[6] + a[7]));
    float n01 = fminf(a[0], a[1]), n23 = fminf(a[2], a[3]);
    float n45 = fminf(a[4], a[5]), n67 = fminf(a[6], a[7]);
    float amin = fminf(fminf(n01, n23), fminf(n45, n67));
    unsigned nm = 0;
    #pragma unroll
    for (int k = 0; k < 8; k++) nm |= (a[k] == amin) ? (1u << k) : 0u;
    int imin = __ffs(nm) - 1;

    unsigned par = __popc(smask) & 1u;

    float pairDot = a1 + a2;
    float halfDot = 0.5f * s - (par ? amin : 0.0f);
    bool usePair = pairDot >= halfDot;

    // --- pair index: i<j among {i1,i2}; sign bits from smask ---
    int i = min(i1, i2), j = max(i1, i2);
    int pidx = i * 7 - ((i * (i - 1)) >> 1) + (j - i - 1);
    unsigned si = (smask >> i) & 1u, sj = (smask >> j) & 1u;
    int idxPair = 4 * pidx + 2 * (int)si + (int)sj;

    // --- half index: flip sign of min component if parity odd ---
    unsigned hv = rmask ^ (par << (7 - imin));
    int idxHalf = 112 + (int)(hv >> 1);

    #pragma unroll
    for (int k = 0; k < 8; k++) {
        float sgn = ((smask >> k) & 1u) ? -1.0f : 1.0f;
        float pairRoot = ((k == i1) | (k == i2)) ? sgn : 0.0f;
        float halfRoot = ((hv >> (7 - k)) & 1u) ? -0.5f : 0.5f;
        root_out[k] = usePair ? pairRoot : halfRoot;
    }
    return usePair ? idxPair : idxHalf;
}

__device__ __forceinline__ void qmul(const float q[4], const float p[4], float o[4]) {
    o[0] = q[0]*p[0] - q[1]*p[1] - q[2]*p[2] - q[3]*p[3];
    o[1] = q[0]*p[1] + q[1]*p[0] + q[2]*p[3] - q[3]*p[2];
    o[2] = q[0]*p[2] - q[1]*p[3] + q[2]*p[0] + q[3]*p[1];
    o[3] = q[0]*p[3] + q[1]*p[2] - q[2]*p[1] + q[3]*p[0];
}

__global__ void __launch_bounds__(TPB)
fused_kernel(const float* __restrict__ states,
             float* __restrict__ out,
             const int* __restrict__ li,
             const int* __restrict__ lj,
             const int* __restrict__ lk,
             float* __restrict__ prod_out,
             float* __restrict__ align_out,
             float* __restrict__ qerr_out,
             float* __restrict__ fano_out,
             int nrows, size_t off_idx,
             double inv_nq, double inv_nf,
             unsigned nblocks) {
    __shared__ float sq[BPB * SQ_STRIDE];   // quantized rows: sq[b][h*8+k]

    int tid = threadIdx.x;
    int row = blockIdx.x * TPB + tid;       // global row index (phase 1)
    int b_local = tid / 7;                  // compile-time 7 -> fast
    int sub     = tid - b_local * 7;        // head (phase1) / line (phase2)

    // ---------------- Phase 1: residual E8 quantization ----------------
    double qe = 0.0;
    if (row < nrows) {
        float x[8];
        const float4* p = reinterpret_cast<const float4*>(states + (size_t)row * 8);
        float4 v0 = p[0], v1 = p[1];
        x[0] = v0.x; x[1] = v0.y; x[2] = v0.z; x[3] = v0.w;
        x[4] = v1.x; x[5] = v1.y; x[6] = v1.z; x[7] = v1.w;

        float res[8], root[8], qsum[8];
        #pragma unroll
        for (int k = 0; k < 8; k++) res[k] = x[k];

        int idx0 = e8_nearest(res, root);
        #pragma unroll
        for (int k = 0; k < 8; k++) { qsum[k] = root[k]; res[k] = x[k] - qsum[k]; }

        int idx1 = e8_nearest(res, root);
        float qef = 0.0f;
        #pragma unroll
        for (int k = 0; k < 8; k++) {
            qsum[k] += root[k];
            float d = x[k] - qsum[k];
            qef += d * d;
        }
        qe = (double)qef;

        // stash in smem for phase 2 (tid -> (b_local, head=sub))
        float* sp = sq + b_local * SQ_STRIDE + sub * 8;
        #pragma unroll
        for (int k = 0; k < 8; k++) sp[k] = qsum[k];

        // global outputs (all coalesced)
        float4 q0, q1;
        q0.x = qsum[0]; q0.y = qsum[1]; q0.z = qsum[2]; q0.w = qsum[3];
        q1.x = qsum[4]; q1.y = qsum[5]; q1.z = qsum[6]; q1.w = qsum[7];
        float4* po = reinterpret_cast<float4*>(out + (size_t)row * 8);
        po[0] = q0; po[1] = q1;

        out[off_idx + row]                 = (float)idx0;
        out[off_idx + (size_t)nrows + row] = (float)idx1;
    }
    __syncthreads();

    // ---------------- Phase 2: Fano octonion alignment ----------------
    // tid -> (b_local, line=sub); global t = blockIdx.x*TPB + tid (contiguous)
    double fs = 0.0;
    if (row < nrows) {
        int hi = __ldg(li + sub), hj = __ldg(lj + sub), hk = __ldg(lk + sub);
        const float* base = sq + b_local * SQ_STRIDE;
        const float* av = base + hi * 8;
        const float* bv = base + hj * 8;
        const float* cv = base + hk * 8;

        float aq[4] = {av[0], av[1], av[2], av[3]};
        float bq[4] = {av[4], av[5], av[6], av[7]};
        float cq[4] = {bv[0], bv[1], bv[2], bv[3]};
        float dq[4] = {bv[4], bv[5], bv[6], bv[7]};
        float dconj[4] = {dq[0], -dq[1], -dq[2], -dq[3]};
        float cconj[4] = {cq[0], -cq[1], -cq[2], -cq[3]};

        float t1[4], t2[4], t3[4], t4[4], pr[8];
        qmul(aq, cq, t1);
        qmul(dconj, bq, t2);
        qmul(dq, aq, t3);
        qmul(bq, cconj, t4);
        #pragma unroll
        for (int k = 0; k < 4; k++) {
            pr[k]     = t1[k] - t2[k];
            pr[4 + k] = t3[k] + t4[k];
        }

        float dot = 0.0f, np2 = 0.0f, nc2 = 0.0f;
        #pragma unroll
        for (int k = 0; k < 8; k++) {
            float c = cv[k];
            dot += pr[k] * c;
            np2 += pr[k] * pr[k];
            nc2 += c * c;
        }
        float denom = fmaxf(sqrtf(np2) * sqrtf(nc2), 1e-8f);
        float align = dot / denom;

        size_t t = (size_t)blockIdx.x * TPB + tid;
        // products region starts at odd float offset -> scalar stores
        float* pw = prod_out + t * 8;
        #pragma unroll
        for (int k = 0; k < 8; k++) pw[k] = pr[k];
        align_out[t] = align;

        float ac = fminf(fmaxf(align, -1.0f), 1.0f);
        fs = (double)(1.0f - ac);
    }

    // ---------------- Reductions + last-block finalize ----------------
    double bq_ = blockReduceSumD(qe);
    __syncthreads();
    double bf_ = blockReduceSumD(fs);

    __shared__ bool amLast;
    if (tid == 0) {
        atomicAdd(&g_qerr_sum, bq_);
        atomicAdd(&g_fano_sum, bf_);
        __threadfence();
        unsigned done = atomicAdd(&g_count, 1u);
        amLast = (done == nblocks - 1);
    }
    __syncthreads();
    if (amLast && tid == 0) {
        double tq = *((volatile double*)&g_qerr_sum);
        double tf = *((volatile double*)&g_fano_sum);
        *qerr_out = (float)(tq * inv_nq);
        double fl = tf * inv_nf * 0.5;
        if (fl < 0.0) fl = 0.0;
        if (fl > 1.0) fl = 1.0;
        *fano_out = (float)fl;
        g_qerr_sum = 0.0;
        g_fano_sum = 0.0;
        g_count = 0;
    }
}

extern "C" void kernel_launch(void* const* d_in, const int* in_sizes, int n_in,
                              void* d_out, int out_size) {
    const float* states = (const float*)d_in[0];
    // d_in[1] = roots (structure known analytically; not needed)
    const int* li = (const int*)d_in[2];
    const int* lj = (const int*)d_in[3];
    const int* lk = (const int*)d_in[4];

    int B = in_sizes[0] / (HH * 8);      // 65536
    int nrows = B * HH;                  // 458752

    float* out = (float*)d_out;
    size_t off_idx   = (size_t)nrows * 8;                 // quantized_ste
    size_t off_qerr  = off_idx + 2 * (size_t)nrows;       // indices (2, B, H)
    size_t off_prod  = off_qerr + 1;                      // q_err scalar
    size_t off_align = off_prod + (size_t)B * LL * 8;     // products (B, L, 8)
    size_t off_fano  = off_align + (size_t)B * LL;        // alignments (B, L)

    unsigned nblocks = (unsigned)((nrows + TPB - 1) / TPB);   // 2048

    fused_kernel<<<nblocks, TPB>>>(states, out, li, lj, lk,
                                   out + off_prod, out + off_align,
                                   out + off_qerr, out + off_fano,
                                   nrows, off_idx,
                                   1.0 / ((double)nrows * 8.0),
                                   1.0 / ((double)B * (double)LL),
                                   nblocks);
}

// round 5
// speedup vs baseline: 1.8265x; 1.1722x over previous
#include <cuda_runtime.h>
#include <math.h>

#define HH 7           // heads per state (Fano plane points)
#define LL 7           // Fano lines
#define BPB 32         // states (b) per block
#define TPB (BPB * 7)  // 224 threads
#define SQ_STRIDE 57   // 7*8 floats per state +1 (odd -> conflict-free phase2 reads)
#define PR_STRIDE 9    // 8 floats +1 pad for product staging

__device__ double g_qerr_sum = 0.0;
__device__ double g_fano_sum = 0.0;
__device__ unsigned g_count = 0;

__inline__ __device__ double blockReduceSumD(double val) {
    __shared__ double sh[32];
    int lane = threadIdx.x & 31;
    int wid  = threadIdx.x >> 5;
    #pragma unroll
    for (int o = 16; o > 0; o >>= 1)
        val += __shfl_down_sync(0xffffffffu, val, o);
    if (lane == 0) sh[wid] = val;
    __syncthreads();
    int nw = (blockDim.x + 31) >> 5;
    val = (threadIdx.x < nw) ? sh[lane] : 0.0;
    if (wid == 0) {
        #pragma unroll
        for (int o = 16; o > 0; o >>= 1)
            val += __shfl_down_sync(0xffffffffu, val, o);
    }
    return val;
}

// Branchless closed-form nearest E8 root. All 240 roots have |r|^2=2, so
// nearest = argmax<residual,root>, computed analytically from root structure.
__device__ __forceinline__ int e8_nearest(const float r[8], float root_out[8]) {
    float a[8];
    unsigned smask = 0;   // sign bits, bit k
    unsigned rmask = 0;   // sign bits, bit (7-k)  (root-list enumeration order)
    #pragma unroll
    for (int k = 0; k < 8; k++) {
        unsigned sb = __float_as_uint(r[k]) >> 31;
        smask |= sb << k;
        rmask |= sb << (7 - k);
        a[k] = fabsf(r[k]);
    }

    // --- max (tree) + first index achieving it ---
    float m01 = fmaxf(a[0], a[1]), m23 = fmaxf(a[2], a[3]);
    float m45 = fmaxf(a[4], a[5]), m67 = fmaxf(a[6], a[7]);
    float a1 = fmaxf(fmaxf(m01, m23), fmaxf(m45, m67));
    unsigned em = 0;
    #pragma unroll
    for (int k = 0; k < 8; k++) em |= (a[k] == a1) ? (1u << k) : 0u;
    int i1 = __ffs(em) - 1;

    // --- second max: exclude i1 (a[] >= 0, so -1 acts as -inf) ---
    float b0 = (i1 == 0) ? -1.0f : a[0], b1 = (i1 == 1) ? -1.0f : a[1];
    float b2 = (i1 == 2) ? -1.0f : a[2], b3 = (i1 == 3) ? -1.0f : a[3];
    float b4 = (i1 == 4) ? -1.0f : a[4], b5 = (i1 == 5) ? -1.0f : a[5];
    float b6 = (i1 == 6) ? -1.0f : a[6], b7 = (i1 == 7) ? -1.0f : a[7];
    float a2 = fmaxf(fmaxf(fmaxf(b0, b1), fmaxf(b2, b3)),
                     fmaxf(fmaxf(b4, b5), fmaxf(b6, b7)));
    unsigned em2 = 0;
    em2 |= (b0 == a2) ? 1u : 0u;        em2 |= (b1 == a2) ? 2u : 0u;
    em2 |= (b2 == a2) ? 4u : 0u;        em2 |= (b3 == a2) ? 8u : 0u;
    em2 |= (b4 == a2) ? 16u : 0u;       em2 |= (b5 == a2) ? 32u : 0u;
    em2 |= (b6 == a2) ? 64u : 0u;       em2 |= (b7 == a2) ? 128u : 0u;
    int i2 = __ffs(em2) - 1;

    // --- sum, min + first index achieving it, parity ---
    float s = ((a[0] + a[1]) + (a[2] + a[3])) + ((a[4] + a[5]) + (a[6] + a[7]));
    float n01 = fminf(a[0], a[1]), n23 = fminf(a[2], a[3]);
    float n45 = fminf(a[4], a[5]), n67 = fminf(a[6], a[7]);
    float amin = fminf(fminf(n01, n23), fminf(n45, n67));
    unsigned nm = 0;
    #pragma unroll
    for (int k = 0; k < 8; k++) nm |= (a[k] == amin) ? (1u << k) : 0u;
    int imin = __ffs(nm) - 1;

    unsigned par = __popc(smask) & 1u;

    float pairDot = a1 + a2;
    float halfDot = 0.5f * s - (par ? amin : 0.0f);
    bool usePair = pairDot >= halfDot;

    // --- pair index: i<j among {i1,i2}; sign bits from smask ---
    int i = min(i1, i2), j = max(i1, i2);
    int pidx = i * 7 - ((i * (i - 1)) >> 1) + (j - i - 1);
    unsigned si = (smask >> i) & 1u, sj = (smask >> j) & 1u;
    int idxPair = 4 * pidx + 2 * (int)si + (int)sj;

    // --- half index: flip sign of min component if parity odd ---
    unsigned hv = rmask ^ (par << (7 - imin));
    int idxHalf = 112 + (int)(hv >> 1);

    #pragma unroll
    for (int k = 0; k < 8; k++) {
        float sgn = ((smask >> k) & 1u) ? -1.0f : 1.0f;
        float pairRoot = ((k == i1) | (k == i2)) ? sgn : 0.0f;
        float halfRoot = ((hv >> (7 - k)) & 1u) ? -0.5f : 0.5f;
        root_out[k] = usePair ? pairRoot : halfRoot;
    }
    return usePair ? idxPair : idxHalf;
}

__device__ __forceinline__ void qmul(const float q[4], const float p[4], float o[4]) {
    o[0] = q[0]*p[0] - q[1]*p[1] - q[2]*p[2] - q[3]*p[3];
    o[1] = q[0]*p[1] + q[1]*p[0] + q[2]*p[3] - q[3]*p[2];
    o[2] = q[0]*p[2] - q[1]*p[3] + q[2]*p[0] + q[3]*p[1];
    o[3] = q[0]*p[3] + q[1]*p[2] - q[2]*p[1] + q[3]*p[0];
}

__global__ void __launch_bounds__(TPB)
fused_kernel(const float* __restrict__ states,
             float* __restrict__ out,
             const int* __restrict__ li,
             const int* __restrict__ lj,
             const int* __restrict__ lk,
             float* __restrict__ prod_out,
             float* __restrict__ align_out,
             float* __restrict__ qerr_out,
             float* __restrict__ fano_out,
             int nrows, size_t off_idx,
             double inv_nq, double inv_nf,
             unsigned nblocks) {
    __shared__ float sq[BPB * SQ_STRIDE];    // quantized rows: sq[b][h*8+k]
    __shared__ float prs[TPB * PR_STRIDE];   // staged products (stride 9)

    int tid = threadIdx.x;
    int row = blockIdx.x * TPB + tid;        // global row index (phase 1)
    int b_local = tid / 7;
    int sub     = tid - b_local * 7;         // head (phase1) / line (phase2)
    int rem     = nrows - blockIdx.x * TPB;  // valid rows in this block (>= TPB normally)

    // ---------------- Phase 1: residual E8 quantization ----------------
    double qe = 0.0;
    if (tid < rem) {
        float x[8];
        const float4* p = reinterpret_cast<const float4*>(states + (size_t)row * 8);
        float4 v0 = p[0], v1 = p[1];
        x[0] = v0.x; x[1] = v0.y; x[2] = v0.z; x[3] = v0.w;
        x[4] = v1.x; x[5] = v1.y; x[6] = v1.z; x[7] = v1.w;

        float res[8], root[8], qsum[8];
        #pragma unroll
        for (int k = 0; k < 8; k++) res[k] = x[k];

        int idx0 = e8_nearest(res, root);
        #pragma unroll
        for (int k = 0; k < 8; k++) { qsum[k] = root[k]; res[k] = x[k] - qsum[k]; }

        int idx1 = e8_nearest(res, root);
        float qef = 0.0f;
        #pragma unroll
        for (int k = 0; k < 8; k++) {
            qsum[k] += root[k];
            float d = x[k] - qsum[k];
            qef += d * d;
        }
        qe = (double)qef;

        // stash in smem (global q writeout happens coalesced below)
        float* sp = sq + b_local * SQ_STRIDE + sub * 8;
        #pragma unroll
        for (int k = 0; k < 8; k++) sp[k] = qsum[k];

        // indices: stride-1 coalesced
        out[off_idx + row]                 = (float)idx0;
        out[off_idx + (size_t)nrows + row] = (float)idx1;
    }
    __syncthreads();

    // ---------------- Coalesced q writeout from smem (float4-dense) -----
    {
        size_t base_f = (size_t)blockIdx.x * TPB * 8;   // block's q region (floats)
        float4* qout = reinterpret_cast<float4*>(out + base_f);
        #pragma unroll
        for (int jj = 0; jj < 2; jj++) {
            int s = tid + jj * TPB;          // float4 slot in block region
            int f = s * 4;                   // float offset in block region
            if (f < rem * 8) {
                int rl = f >> 3;             // local row
                int k0 = f & 7;
                int bl = rl / 7;
                int h  = rl - bl * 7;
                const float* spp = sq + bl * SQ_STRIDE + h * 8 + k0;
                qout[s] = make_float4(spp[0], spp[1], spp[2], spp[3]);
            }
        }
    }

    // ---------------- Phase 2: Fano octonion alignment (from smem) ------
    double fs = 0.0;
    if (tid < rem) {
        int hi = __ldg(li + sub), hj = __ldg(lj + sub), hk = __ldg(lk + sub);
        const float* base = sq + b_local * SQ_STRIDE;
        const float* av = base + hi * 8;
        const float* bv = base + hj * 8;
        const float* cv = base + hk * 8;

        float aq[4] = {av[0], av[1], av[2], av[3]};
        float bq[4] = {av[4], av[5], av[6], av[7]};
        float cq[4] = {bv[0], bv[1], bv[2], bv[3]};
        float dq[4] = {bv[4], bv[5], bv[6], bv[7]};
        float dconj[4] = {dq[0], -dq[1], -dq[2], -dq[3]};
        float cconj[4] = {cq[0], -cq[1], -cq[2], -cq[3]};

        float t1[4], t2[4], t3[4], t4[4], pr[8];
        qmul(aq, cq, t1);
        qmul(dconj, bq, t2);
        qmul(dq, aq, t3);
        qmul(bq, cconj, t4);
        float dot = 0.0f, np2 = 0.0f, nc2 = 0.0f;
        float* pw = prs + tid * PR_STRIDE;
        #pragma unroll
        for (int k = 0; k < 4; k++) {
            float plo = t1[k] - t2[k];
            float phi = t3[k] + t4[k];
            pr[k] = plo; pr[4 + k] = phi;
        }
        #pragma unroll
        for (int k = 0; k < 8; k++) {
            float c = cv[k];
            dot += pr[k] * c;
            np2 += pr[k] * pr[k];
            nc2 += c * c;
            pw[k] = pr[k];
        }
        float align = dot * rsqrtf(fmaxf(np2 * nc2, 1e-16f));

        size_t t = (size_t)blockIdx.x * TPB + tid;
        align_out[t] = align;   // stride-1 coalesced

        float ac = fminf(fmaxf(align, -1.0f), 1.0f);
        fs = (double)(1.0f - ac);
    }
    __syncthreads();

    // ---------------- Coalesced products writeout (dense stride-TPB) ----
    {
        size_t base_f = (size_t)blockIdx.x * TPB * 8;
        #pragma unroll
        for (int jj = 0; jj < 8; jj++) {
            int f = tid + jj * TPB;          // float offset in block's 1792-float region
            if (f < rem * 8) {
                int ts = f >> 3;
                int k  = f & 7;
                prod_out[base_f + f] = prs[ts * PR_STRIDE + k];
            }
        }
    }

    // ---------------- Reductions + last-block finalize ----------------
    double bq_ = blockReduceSumD(qe);
    __syncthreads();
    double bf_ = blockReduceSumD(fs);

    __shared__ bool amLast;
    if (tid == 0) {
        atomicAdd(&g_qerr_sum, bq_);
        atomicAdd(&g_fano_sum, bf_);
        __threadfence();
        unsigned done = atomicAdd(&g_count, 1u);
        amLast = (done == nblocks - 1);
    }
    __syncthreads();
    if (amLast && tid == 0) {
        double tq = *((volatile double*)&g_qerr_sum);
        double tf = *((volatile double*)&g_fano_sum);
        *qerr_out = (float)(tq * inv_nq);
        double fl = tf * inv_nf * 0.5;
        if (fl < 0.0) fl = 0.0;
        if (fl > 1.0) fl = 1.0;
        *fano_out = (float)fl;
        g_qerr_sum = 0.0;
        g_fano_sum = 0.0;
        g_count = 0;
    }
}

extern "C" void kernel_launch(void* const* d_in, const int* in_sizes, int n_in,
                              void* d_out, int out_size) {
    const float* states = (const float*)d_in[0];
    // d_in[1] = roots (structure known analytically; not needed)
    const int* li = (const int*)d_in[2];
    const int* lj = (const int*)d_in[3];
    const int* lk = (const int*)d_in[4];

    int B = in_sizes[0] / (HH * 8);      // 65536
    int nrows = B * HH;                  // 458752 = 224 * 2048

    float* out = (float*)d_out;
    size_t off_idx   = (size_t)nrows * 8;                 // quantized_ste
    size_t off_qerr  = off_idx + 2 * (size_t)nrows;       // indices (2, B, H)
    size_t off_prod  = off_qerr + 1;                      // q_err scalar
    size_t off_align = off_prod + (size_t)B * LL * 8;     // products (B, L, 8)
    size_t off_fano  = off_align + (size_t)B * LL;        // alignments (B, L)

    unsigned nblocks = (unsigned)((nrows + TPB - 1) / TPB);   // 2048

    fused_kernel<<<nblocks, TPB>>>(states, out, li, lj, lk,
                                   out + off_prod, out + off_align,
                                   out + off_qerr, out + off_fano,
                                   nrows, off_idx,
                                   1.0 / ((double)nrows * 8.0),
                                   1.0 / ((double)B * (double)LL),
                                   nblocks);
}

// round 6
// speedup vs baseline: 1.9889x; 1.0889x over previous
#include <cuda_runtime.h>
#include <math.h>

#define HH 7           // heads per state (Fano plane points)
#define LL 7           // Fano lines
#define BPB 32         // states (b) per block
#define TPB (BPB * 7)  // 224 threads
#define SQ_STRIDE 57   // 7*8 floats per state +1 (odd -> conflict-free phase2 reads)
#define PR_STRIDE 9    // 8 floats +1 pad for product staging

__device__ double g_qerr_sum = 0.0;
__device__ double g_fano_sum = 0.0;
__device__ unsigned g_count = 0;

// fp32 block reduction (block-local values are O(1), 224 elements -> ~1e-6 rel err;
// cross-block accumulation stays in double via one atomicAdd per block)
__inline__ __device__ float blockReduceSumF(float val) {
    __shared__ float sh[32];
    int lane = threadIdx.x & 31;
    int wid  = threadIdx.x >> 5;
    #pragma unroll
    for (int o = 16; o > 0; o >>= 1)
        val += __shfl_down_sync(0xffffffffu, val, o);
    if (lane == 0) sh[wid] = val;
    __syncthreads();
    int nw = (blockDim.x + 31) >> 5;
    val = (threadIdx.x < nw) ? sh[lane] : 0.0f;
    if (wid == 0) {
        #pragma unroll
        for (int o = 16; o > 0; o >>= 1)
            val += __shfl_down_sync(0xffffffffu, val, o);
    }
    return val;
}

// Branchless closed-form nearest E8 root. All 240 roots have |r|^2=2, so
// nearest = argmax<residual,root>, computed analytically from root structure.
__device__ __forceinline__ int e8_nearest(const float r[8], float root_out[8]) {
    float a[8];
    unsigned smask = 0;   // sign bits, bit k
    unsigned rmask = 0;   // sign bits, bit (7-k)  (root-list enumeration order)
    #pragma unroll
    for (int k = 0; k < 8; k++) {
        unsigned sb = __float_as_uint(r[k]) >> 31;
        smask |= sb << k;
        rmask |= sb << (7 - k);
        a[k] = fabsf(r[k]);
    }

    // --- max (tree) + first index achieving it ---
    float m01 = fmaxf(a[0], a[1]), m23 = fmaxf(a[2], a[3]);
    float m45 = fmaxf(a[4], a[5]), m67 = fmaxf(a[6], a[7]);
    float a1 = fmaxf(fmaxf(m01, m23), fmaxf(m45, m67));
    unsigned em = 0;
    #pragma unroll
    for (int k = 0; k < 8; k++) em |= (a[k] == a1) ? (1u << k) : 0u;
    int i1 = __ffs(em) - 1;

    // --- second max: exclude i1 (a[] >= 0, so -1 acts as -inf) ---
    float b0 = (i1 == 0) ? -1.0f : a[0], b1 = (i1 == 1) ? -1.0f : a[1];
    float b2 = (i1 == 2) ? -1.0f : a[2], b3 = (i1 == 3) ? -1.0f : a[3];
    float b4 = (i1 == 4) ? -1.0f : a[4], b5 = (i1 == 5) ? -1.0f : a[5];
    float b6 = (i1 == 6) ? -1.0f : a[6], b7 = (i1 == 7) ? -1.0f : a[7];
    float a2 = fmaxf(fmaxf(fmaxf(b0, b1), fmaxf(b2, b3)),
                     fmaxf(fmaxf(b4, b5), fmaxf(b6, b7)));
    unsigned em2 = 0;
    em2 |= (b0 == a2) ? 1u : 0u;        em2 |= (b1 == a2) ? 2u : 0u;
    em2 |= (b2 == a2) ? 4u : 0u;        em2 |= (b3 == a2) ? 8u : 0u;
    em2 |= (b4 == a2) ? 16u : 0u;       em2 |= (b5 == a2) ? 32u : 0u;
    em2 |= (b6 == a2) ? 64u : 0u;       em2 |= (b7 == a2) ? 128u : 0u;
    int i2 = __ffs(em2) - 1;

    // --- sum, min + first index achieving it, parity ---
    float s = ((a[0] + a[1]) + (a[2] + a[3])) + ((a[4] + a[5]) + (a[6] + a[7]));
    float n01 = fminf(a[0], a[1]), n23 = fminf(a[2], a[3]);
    float n45 = fminf(a[4], a[5]), n67 = fminf(a[6], a[7]);
    float amin = fminf(fminf(n01, n23), fminf(n45, n67));
    unsigned nm = 0;
    #pragma unroll
    for (int k = 0; k < 8; k++) nm |= (a[k] == amin) ? (1u << k) : 0u;
    int imin = __ffs(nm) - 1;

    unsigned par = __popc(smask) & 1u;

    float pairDot = a1 + a2;
    float halfDot = 0.5f * s - (par ? amin : 0.0f);
    bool usePair = pairDot >= halfDot;

    // --- pair index: i<j among {i1,i2}; sign bits from smask ---
    int i = min(i1, i2), j = max(i1, i2);
    int pidx = i * 7 - ((i * (i - 1)) >> 1) + (j - i - 1);
    unsigned si = (smask >> i) & 1u, sj = (smask >> j) & 1u;
    int idxPair = 4 * pidx + 2 * (int)si + (int)sj;

    // --- half index: flip sign of min component if parity odd ---
    unsigned hv = rmask ^ (par << (7 - imin));
    int idxHalf = 112 + (int)(hv >> 1);

    #pragma unroll
    for (int k = 0; k < 8; k++) {
        float sgn = ((smask >> k) & 1u) ? -1.0f : 1.0f;
        float pairRoot = ((k == i1) | (k == i2)) ? sgn : 0.0f;
        float halfRoot = ((hv >> (7 - k)) & 1u) ? -0.5f : 0.5f;
        root_out[k] = usePair ? pairRoot : halfRoot;
    }
    return usePair ? idxPair : idxHalf;
}

__device__ __forceinline__ void qmul(const float q[4], const float p[4], float o[4]) {
    o[0] = q[0]*p[0] - q[1]*p[1] - q[2]*p[2] - q[3]*p[3];
    o[1] = q[0]*p[1] + q[1]*p[0] + q[2]*p[3] - q[3]*p[2];
    o[2] = q[0]*p[2] - q[1]*p[3] + q[2]*p[0] + q[3]*p[1];
    o[3] = q[0]*p[3] + q[1]*p[2] - q[2]*p[1] + q[3]*p[0];
}

__global__ void __launch_bounds__(TPB, 6)
fused_kernel(const float* __restrict__ states,
             float* __restrict__ out,
             const int* __restrict__ li,
             const int* __restrict__ lj,
             const int* __restrict__ lk,
             float* __restrict__ prod_out,
             float* __restrict__ align_out,
             float* __restrict__ qerr_out,
             float* __restrict__ fano_out,
             int nrows, size_t off_idx,
             double inv_nq, double inv_nf,
             unsigned nblocks) {
    __shared__ float sq[BPB * SQ_STRIDE];    // quantized rows: sq[b][h*8+k]
    __shared__ float prs[TPB * PR_STRIDE];   // staged products (stride 9)

    int tid = threadIdx.x;
    int row = blockIdx.x * TPB + tid;        // global row index (phase 1)
    int b_local = tid / 7;
    int sub     = tid - b_local * 7;         // head (phase1) / line (phase2)
    int rem     = nrows - blockIdx.x * TPB;  // valid rows in this block

    // ---------------- Phase 1: residual E8 quantization ----------------
    float qe = 0.0f;
    if (tid < rem) {
        float x[8];
        const float4* p = reinterpret_cast<const float4*>(states + (size_t)row * 8);
        float4 v0 = p[0], v1 = p[1];
        x[0] = v0.x; x[1] = v0.y; x[2] = v0.z; x[3] = v0.w;
        x[4] = v1.x; x[5] = v1.y; x[6] = v1.z; x[7] = v1.w;

        float res[8], root[8], qsum[8];
        #pragma unroll
        for (int k = 0; k < 8; k++) res[k] = x[k];

        int idx0 = e8_nearest(res, root);
        #pragma unroll
        for (int k = 0; k < 8; k++) { qsum[k] = root[k]; res[k] = x[k] - qsum[k]; }

        int idx1 = e8_nearest(res, root);
        #pragma unroll
        for (int k = 0; k < 8; k++) {
            qsum[k] += root[k];
            float d = x[k] - qsum[k];
            qe += d * d;
        }

        // stash in smem (global q writeout happens coalesced below)
        float* sp = sq + b_local * SQ_STRIDE + sub * 8;
        #pragma unroll
        for (int k = 0; k < 8; k++) sp[k] = qsum[k];

        // indices: stride-1 coalesced
        out[off_idx + row]                 = (float)idx0;
        out[off_idx + (size_t)nrows + row] = (float)idx1;
    }
    __syncthreads();

    // ---------------- Coalesced q writeout from smem (float4-dense) -----
    {
        size_t base_f = (size_t)blockIdx.x * TPB * 8;   // block's q region (floats)
        float4* qout = reinterpret_cast<float4*>(out + base_f);
        #pragma unroll
        for (int jj = 0; jj < 2; jj++) {
            int s = tid + jj * TPB;          // float4 slot in block region
            int f = s * 4;                   // float offset in block region
            if (f < rem * 8) {
                int rl = f >> 3;             // local row
                int k0 = f & 7;
                int bl = rl / 7;
                int h  = rl - bl * 7;
                const float* spp = sq + bl * SQ_STRIDE + h * 8 + k0;
                qout[s] = make_float4(spp[0], spp[1], spp[2], spp[3]);
            }
        }
    }

    // ---------------- Phase 2: Fano octonion alignment (from smem) ------
    float fsv = 0.0f;
    if (tid < rem) {
        int hi = __ldg(li + sub), hj = __ldg(lj + sub), hk = __ldg(lk + sub);
        const float* base = sq + b_local * SQ_STRIDE;
        const float* av = base + hi * 8;
        const float* bv = base + hj * 8;
        const float* cv = base + hk * 8;

        float aq[4] = {av[0], av[1], av[2], av[3]};
        float bq[4] = {av[4], av[5], av[6], av[7]};
        float cq[4] = {bv[0], bv[1], bv[2], bv[3]};
        float dq[4] = {bv[4], bv[5], bv[6], bv[7]};
        float dconj[4] = {dq[0], -dq[1], -dq[2], -dq[3]};
        float cconj[4] = {cq[0], -cq[1], -cq[2], -cq[3]};

        float t1[4], t2[4], t3[4], t4[4];
        qmul(aq, cq, t1);
        qmul(dconj, bq, t2);
        qmul(dq, aq, t3);
        qmul(bq, cconj, t4);

        float dot = 0.0f, np2 = 0.0f, nc2 = 0.0f;
        float* pw = prs + tid * PR_STRIDE;
        #pragma unroll
        for (int k = 0; k < 4; k++) {
            float plo = t1[k] - t2[k];
            float phi = t3[k] + t4[k];
            float clo = cv[k], chi = cv[4 + k];
            dot += plo * clo + phi * chi;
            np2 += plo * plo + phi * phi;
            nc2 += clo * clo + chi * chi;
            pw[k]     = plo;
            pw[4 + k] = phi;
        }
        float align = dot * rsqrtf(fmaxf(np2 * nc2, 1e-16f));

        size_t t = (size_t)blockIdx.x * TPB + tid;
        align_out[t] = align;   // stride-1 coalesced

        float ac = fminf(fmaxf(align, -1.0f), 1.0f);
        fsv = 1.0f - ac;
    }
    __syncthreads();

    // ---------------- Coalesced products writeout (dense stride-TPB) ----
    {
        size_t base_f = (size_t)blockIdx.x * TPB * 8;
        #pragma unroll
        for (int jj = 0; jj < 8; jj++) {
            int f = tid + jj * TPB;          // float offset in block's 1792-float region
            if (f < rem * 8) {
                int ts = f >> 3;
                int k  = f & 7;
                prod_out[base_f + f] = prs[ts * PR_STRIDE + k];
            }
        }
    }

    // ---------------- Reductions + last-block finalize ----------------
    float bq_ = blockReduceSumF(qe);
    __syncthreads();
    float bf_ = blockReduceSumF(fsv);

    __shared__ bool amLast;
    if (tid == 0) {
        atomicAdd(&g_qerr_sum, (double)bq_);
        atomicAdd(&g_fano_sum, (double)bf_);
        __threadfence();
        unsigned done = atomicAdd(&g_count, 1u);
        amLast = (done == nblocks - 1);
    }
    __syncthreads();
    if (amLast && tid == 0) {
        double tq = *((volatile double*)&g_qerr_sum);
        double tf = *((volatile double*)&g_fano_sum);
        *qerr_out = (float)(tq * inv_nq);
        double fl = tf * inv_nf * 0.5;
        if (fl < 0.0) fl = 0.0;
        if (fl > 1.0) fl = 1.0;
        *fano_out = (float)fl;
        g_qerr_sum = 0.0;
        g_fano_sum = 0.0;
        g_count = 0;
    }
}

extern "C" void kernel_launch(void* const* d_in, const int* in_sizes, int n_in,
                              void* d_out, int out_size) {
    const float* states = (const float*)d_in[0];
    // d_in[1] = roots (structure known analytically; not needed)
    const int* li = (const int*)d_in[2];
    const int* lj = (const int*)d_in[3];
    const int* lk = (const int*)d_in[4];

    int B = in_sizes[0] / (HH * 8);      // 65536
    int nrows = B * HH;                  // 458752 = 224 * 2048

    float* out = (float*)d_out;
    size_t off_idx   = (size_t)nrows * 8;                 // quantized_ste
    size_t off_qerr  = off_idx + 2 * (size_t)nrows;       // indices (2, B, H)
    size_t off_prod  = off_qerr + 1;                      // q_err scalar
    size_t off_align = off_prod + (size_t)B * LL * 8;     // products (B, L, 8)
    size_t off_fano  = off_align + (size_t)B * LL;        // alignments (B, L)

    unsigned nblocks = (unsigned)((nrows + TPB - 1) / TPB);   // 2048

    fused_kernel<<<nblocks, TPB>>>(states, out, li, lj, lk,
                                   out + off_prod, out + off_align,
                                   out + off_qerr, out + off_fano,
                                   nrows, off_idx,
                                   1.0 / ((double)nrows * 8.0),
                                   1.0 / ((double)B * (double)LL),
                                   nblocks);
}

// round 7
// speedup vs baseline: 2.1829x; 1.0976x over previous
#include <cuda_runtime.h>
#include <math.h>

#define HH 7           // heads per state (Fano plane points)
#define LL 7           // Fano lines
#define BPB 32         // states (b) per block
#define TPB (BPB * 7)  // 224 threads
#define SQ_STRIDE 57   // 7*8 floats per state +1 (odd -> conflict-free phase2 reads)
#define PR_STRIDE 9    // 8 floats +1 pad (odd -> conflict-free staging writes)

__device__ double g_qerr_sum = 0.0;
__device__ double g_fano_sum = 0.0;
__device__ unsigned g_count = 0;

// Reduce two fp32 values across the block in one pass (224 thr = 7 warps).
__inline__ __device__ void blockReduce2F(float v1, float v2, float& o1, float& o2) {
    __shared__ float s1[8], s2[8];
    int lane = threadIdx.x & 31;
    int wid  = threadIdx.x >> 5;
    #pragma unroll
    for (int o = 16; o > 0; o >>= 1) {
        v1 += __shfl_down_sync(0xffffffffu, v1, o);
        v2 += __shfl_down_sync(0xffffffffu, v2, o);
    }
    if (lane == 0) { s1[wid] = v1; s2[wid] = v2; }
    __syncthreads();
    if (wid == 0) {
        v1 = (lane < (TPB >> 5)) ? s1[lane] : 0.0f;
        v2 = (lane < (TPB >> 5)) ? s2[lane] : 0.0f;
        #pragma unroll
        for (int o = 4; o > 0; o >>= 1) {
            v1 += __shfl_down_sync(0xffffffffu, v1, o);
            v2 += __shfl_down_sync(0xffffffffu, v2, o);
        }
        o1 = v1; o2 = v2;
    }
}

// Branchless closed-form nearest E8 root. All 240 roots have |r|^2=2, so
// nearest = argmax<residual,root>, computed analytically from root structure.
__device__ __forceinline__ int e8_nearest(const float r[8], float root_out[8]) {
    float a[8];
    unsigned smask = 0;   // sign bits, bit k
    unsigned rmask = 0;   // sign bits, bit (7-k)  (root-list enumeration order)
    #pragma unroll
    for (int k = 0; k < 8; k++) {
        unsigned sb = __float_as_uint(r[k]) >> 31;
        smask |= sb << k;
        rmask |= sb << (7 - k);
        a[k] = fabsf(r[k]);
    }

    // --- max (tree) + first index achieving it ---
    float m01 = fmaxf(a[0], a[1]), m23 = fmaxf(a[2], a[3]);
    float m45 = fmaxf(a[4], a[5]), m67 = fmaxf(a[6], a[7]);
    float a1 = fmaxf(fmaxf(m01, m23), fmaxf(m45, m67));
    unsigned em = 0;
    #pragma unroll
    for (int k = 0; k < 8; k++) em |= (a[k] == a1) ? (1u << k) : 0u;
    int i1 = __ffs(em) - 1;

    // --- second max: exclude i1 (a[] >= 0, so -1 acts as -inf) ---
    float b0 = (i1 == 0) ? -1.0f : a[0], b1 = (i1 == 1) ? -1.0f : a[1];
    float b2 = (i1 == 2) ? -1.0f : a[2], b3 = (i1 == 3) ? -1.0f : a[3];
    float b4 = (i1 == 4) ? -1.0f : a[4], b5 = (i1 == 5) ? -1.0f : a[5];
    float b6 = (i1 == 6) ? -1.0f : a[6], b7 = (i1 == 7) ? -1.0f : a[7];
    float a2 = fmaxf(fmaxf(fmaxf(b0, b1), fmaxf(b2, b3)),
                     fmaxf(fmaxf(b4, b5), fmaxf(b6, b7)));
    unsigned em2 = 0;
    em2 |= (b0 == a2) ? 1u : 0u;        em2 |= (b1 == a2) ? 2u : 0u;
    em2 |= (b2 == a2) ? 4u : 0u;        em2 |= (b3 == a2) ? 8u : 0u;
    em2 |= (b4 == a2) ? 16u : 0u;       em2 |= (b5 == a2) ? 32u : 0u;
    em2 |= (b6 == a2) ? 64u : 0u;       em2 |= (b7 == a2) ? 128u : 0u;
    int i2 = __ffs(em2) - 1;

    // --- sum, min + first index achieving it, parity ---
    float s = ((a[0] + a[1]) + (a[2] + a[3])) + ((a[4] + a[5]) + (a[6] + a[7]));
    float n01 = fminf(a[0], a[1]), n23 = fminf(a[2], a[3]);
    float n45 = fminf(a[4], a[5]), n67 = fminf(a[6], a[7]);
    float amin = fminf(fminf(n01, n23), fminf(n45, n67));
    unsigned nm = 0;
    #pragma unroll
    for (int k = 0; k < 8; k++) nm |= (a[k] == amin) ? (1u << k) : 0u;
    int imin = __ffs(nm) - 1;

    unsigned par = __popc(smask) & 1u;

    float pairDot = a1 + a2;
    float halfDot = 0.5f * s - (par ? amin : 0.0f);
    bool usePair = pairDot >= halfDot;

    // --- pair index: i<j among {i1,i2}; sign bits from smask ---
    int i = min(i1, i2), j = max(i1, i2);
    int pidx = i * 7 - ((i * (i - 1)) >> 1) + (j - i - 1);
    unsigned si = (smask >> i) & 1u, sj = (smask >> j) & 1u;
    int idxPair = 4 * pidx + 2 * (int)si + (int)sj;

    // --- half index: flip sign of min component if parity odd ---
    unsigned hv = rmask ^ (par << (7 - imin));
    int idxHalf = 112 + (int)(hv >> 1);

    #pragma unroll
    for (int k = 0; k < 8; k++) {
        float sgn = ((smask >> k) & 1u) ? -1.0f : 1.0f;
        float pairRoot = ((k == i1) | (k == i2)) ? sgn : 0.0f;
        float halfRoot = ((hv >> (7 - k)) & 1u) ? -0.5f : 0.5f;
        root_out[k] = usePair ? pairRoot : halfRoot;
    }
    return usePair ? idxPair : idxHalf;
}

__device__ __forceinline__ void qmul(const float q[4], const float p[4], float o[4]) {
    o[0] = q[0]*p[0] - q[1]*p[1] - q[2]*p[2] - q[3]*p[3];
    o[1] = q[0]*p[1] + q[1]*p[0] + q[2]*p[3] - q[3]*p[2];
    o[2] = q[0]*p[2] - q[1]*p[3] + q[2]*p[0] + q[3]*p[1];
    o[3] = q[0]*p[3] + q[1]*p[2] - q[2]*p[1] + q[3]*p[0];
}

// Shared body; FULL=true -> no bounds predicates (block entirely in range).
template <bool FULL>
__device__ __forceinline__ void fused_body(
        const float* __restrict__ states,
        float* __restrict__ out,
        const int* __restrict__ li,
        const int* __restrict__ lj,
        const int* __restrict__ lk,
        float* __restrict__ prod_out,
        float* __restrict__ align_out,
        int nrows, size_t off_idx, int rem,
        float* sq, float* prs, float& qe, float& fsv) {
    int tid = threadIdx.x;
    int row = blockIdx.x * TPB + tid;
    int b_local = tid / 7;
    int sub     = tid - b_local * 7;

    // ---------------- Phase 1: residual E8 quantization ----------------
    if (FULL || tid < rem) {
        float x[8];
        const float4* p = reinterpret_cast<const float4*>(states + (size_t)row * 8);
        float4 v0 = p[0], v1 = p[1];
        x[0] = v0.x; x[1] = v0.y; x[2] = v0.z; x[3] = v0.w;
        x[4] = v1.x; x[5] = v1.y; x[6] = v1.z; x[7] = v1.w;

        float res[8], root[8], qsum[8];
        #pragma unroll
        for (int k = 0; k < 8; k++) res[k] = x[k];

        int idx0 = e8_nearest(res, root);
        #pragma unroll
        for (int k = 0; k < 8; k++) { qsum[k] = root[k]; res[k] = x[k] - qsum[k]; }

        int idx1 = e8_nearest(res, root);
        #pragma unroll
        for (int k = 0; k < 8; k++) {
            qsum[k] += root[k];
            float d = x[k] - qsum[k];
            qe += d * d;
        }

        float* sp = sq + b_local * SQ_STRIDE + sub * 8;
        #pragma unroll
        for (int k = 0; k < 8; k++) sp[k] = qsum[k];

        out[off_idx + row]                 = (float)idx0;
        out[off_idx + (size_t)nrows + row] = (float)idx1;
    }
    __syncthreads();

    // ---------------- Coalesced q writeout from smem (float4-dense) -----
    {
        size_t base_f = (size_t)blockIdx.x * TPB * 8;
        float4* qout = reinterpret_cast<float4*>(out + base_f);
        // s = tid + jj*TPB; f = 4s; rl = s>>1 (+112/jj); bl = rl/7 (+16/jj);
        // h, k0 constant across jj.
        int rl0 = tid >> 1;
        int bl0 = rl0 / 7;
        int h0  = rl0 - bl0 * 7;
        int k0  = (tid & 1) << 2;
        const float* sp0 = sq + bl0 * SQ_STRIDE + h0 * 8 + k0;
        if (FULL || (tid * 4) < rem * 8)
            qout[tid] = make_float4(sp0[0], sp0[1], sp0[2], sp0[3]);
        const float* sp1 = sp0 + 16 * SQ_STRIDE;
        if (FULL || ((tid + TPB) * 4) < rem * 8)
            qout[tid + TPB] = make_float4(sp1[0], sp1[1], sp1[2], sp1[3]);
    }

    // ---------------- Phase 2: Fano octonion alignment (from smem) ------
    if (FULL || tid < rem) {
        int hi = __ldg(li + sub), hj = __ldg(lj + sub), hk = __ldg(lk + sub);
        const float* base = sq + b_local * SQ_STRIDE;
        const float* av = base + hi * 8;
        const float* bv = base + hj * 8;
        const float* cv = base + hk * 8;

        float aq[4] = {av[0], av[1], av[2], av[3]};
        float bq[4] = {av[4], av[5], av[6], av[7]};
        float cq[4] = {bv[0], bv[1], bv[2], bv[3]};
        float dq[4] = {bv[4], bv[5], bv[6], bv[7]};
        float dconj[4] = {dq[0], -dq[1], -dq[2], -dq[3]};
        float cconj[4] = {cq[0], -cq[1], -cq[2], -cq[3]};

        float t1[4], t2[4], t3[4], t4[4];
        qmul(aq, cq, t1);
        qmul(dconj, bq, t2);
        qmul(dq, aq, t3);
        qmul(bq, cconj, t4);

        float dot = 0.0f, np2 = 0.0f, nc2 = 0.0f;
        float* pw = prs + tid * PR_STRIDE;
        #pragma unroll
        for (int k = 0; k < 4; k++) {
            float plo = t1[k] - t2[k];
            float phi = t3[k] + t4[k];
            float clo = cv[k], chi = cv[4 + k];
            dot += plo * clo + phi * chi;
            np2 += plo * plo + phi * phi;
            nc2 += clo * clo + chi * chi;
            pw[k]     = plo;
            pw[4 + k] = phi;
        }
        float align = dot * rsqrtf(fmaxf(np2 * nc2, 1e-16f));

        align_out[(size_t)blockIdx.x * TPB + tid] = align;

        float ac = fminf(fmaxf(align, -1.0f), 1.0f);
        fsv = 1.0f - ac;
    }
    __syncthreads();

    // ---------------- Coalesced products writeout (dense stride-TPB) ----
    {
        size_t base_f = (size_t)blockIdx.x * TPB * 8;
        // f = tid + jj*TPB; ts = f>>3 (+28/jj); k = tid&7 constant.
        int ts0 = tid >> 3;
        int kk  = tid & 7;
        const float* pp = prs + ts0 * PR_STRIDE + kk;
        float* gp = prod_out + base_f + tid;
        #pragma unroll
        for (int jj = 0; jj < 8; jj++) {
            if (FULL || (tid + jj * TPB) < rem * 8)
                gp[jj * TPB] = pp[jj * 28 * PR_STRIDE];
        }
    }
}

__global__ void __launch_bounds__(TPB, 7)
fused_kernel(const float* __restrict__ states,
             float* __restrict__ out,
             const int* __restrict__ li,
             const int* __restrict__ lj,
             const int* __restrict__ lk,
             float* __restrict__ prod_out,
             float* __restrict__ align_out,
             float* __restrict__ qerr_out,
             float* __restrict__ fano_out,
             int nrows, size_t off_idx,
             double inv_nq, double inv_nf,
             unsigned nblocks) {
    __shared__ float sq[BPB * SQ_STRIDE];
    __shared__ float prs[TPB * PR_STRIDE];

    int rem = nrows - blockIdx.x * TPB;
    float qe = 0.0f, fsv = 0.0f;

    if (rem >= TPB) {
        fused_body<true>(states, out, li, lj, lk, prod_out, align_out,
                         nrows, off_idx, rem, sq, prs, qe, fsv);
    } else {
        fused_body<false>(states, out, li, lj, lk, prod_out, align_out,
                          nrows, off_idx, rem, sq, prs, qe, fsv);
    }

    // ---------------- Reduction + last-block finalize ----------------
    float bq_, bf_;
    blockReduce2F(qe, fsv, bq_, bf_);

    __shared__ bool amLast;
    if (threadIdx.x == 0) {
        atomicAdd(&g_qerr_sum, (double)bq_);
        atomicAdd(&g_fano_sum, (double)bf_);
        __threadfence();
        unsigned done = atomicAdd(&g_count, 1u);
        amLast = (done == nblocks - 1);
    }
    __syncthreads();
    if (amLast && threadIdx.x == 0) {
        double tq = *((volatile double*)&g_qerr_sum);
        double tf = *((volatile double*)&g_fano_sum);
        *qerr_out = (float)(tq * inv_nq);
        double fl = tf * inv_nf * 0.5;
        if (fl < 0.0) fl = 0.0;
        if (fl > 1.0) fl = 1.0;
        *fano_out = (float)fl;
        g_qerr_sum = 0.0;
        g_fano_sum = 0.0;
        g_count = 0;
    }
}

extern "C" void kernel_launch(void* const* d_in, const int* in_sizes, int n_in,
                              void* d_out, int out_size) {
    const float* states = (const float*)d_in[0];
    // d_in[1] = roots (structure known analytically; not needed)
    const int* li = (const int*)d_in[2];
    const int* lj = (const int*)d_in[3];
    const int* lk = (const int*)d_in[4];

    int B = in_sizes[0] / (HH * 8);      // 65536
    int nrows = B * HH;                  // 458752 = 224 * 2048

    float* out = (float*)d_out;
    size_t off_idx   = (size_t)nrows * 8;                 // quantized_ste
    size_t off_qerr  = off_idx + 2 * (size_t)nrows;       // indices (2, B, H)
    size_t off_prod  = off_qerr + 1;                      // q_err scalar
    size_t off_align = off_prod + (size_t)B * LL * 8;     // products (B, L, 8)
    size_t off_fano  = off_align + (size_t)B * LL;        // alignments (B, L)

    unsigned nblocks = (unsigned)((nrows + TPB - 1) / TPB);   // 2048

    fused_kernel<<<nblocks, TPB>>>(states, out, li, lj, lk,
                                   out + off_prod, out + off_align,
                                   out + off_qerr, out + off_fano,
                                   nrows, off_idx,
                                   1.0 / ((double)nrows * 8.0),
                                   1.0 / ((double)B * (double)LL),
                                   nblocks);
}

// round 8
// speedup vs baseline: 2.1863x; 1.0015x over previous
#include <cuda_runtime.h>
#include <math.h>

#define HH 7           // heads per state (Fano plane points)
#define LL 7           // Fano lines
#define BPB 32         // states (b) per block
#define TPB (BPB * 7)  // 224 threads
// UNPADDED strides: smem layouts become exactly linear in tid -> vectorized,
// mostly conflict-free LDS.128/STS.128 and zero div/mod in writeouts.
#define SQ_STRIDE 56   // 7*8 floats per state
#define PR_STRIDE 8    // 8 floats per product

__device__ double g_qerr_sum = 0.0;
__device__ double g_fano_sum = 0.0;
__device__ unsigned g_count = 0;

// Reduce two fp32 values across the block in one pass (224 thr = 7 warps).
__inline__ __device__ void blockReduce2F(float v1, float v2, float& o1, float& o2) {
    __shared__ float s1[8], s2[8];
    int lane = threadIdx.x & 31;
    int wid  = threadIdx.x >> 5;
    #pragma unroll
    for (int o = 16; o > 0; o >>= 1) {
        v1 += __shfl_down_sync(0xffffffffu, v1, o);
        v2 += __shfl_down_sync(0xffffffffu, v2, o);
    }
    if (lane == 0) { s1[wid] = v1; s2[wid] = v2; }
    __syncthreads();
    if (wid == 0) {
        v1 = (lane < (TPB >> 5)) ? s1[lane] : 0.0f;
        v2 = (lane < (TPB >> 5)) ? s2[lane] : 0.0f;
        #pragma unroll
        for (int o = 4; o > 0; o >>= 1) {
            v1 += __shfl_down_sync(0xffffffffu, v1, o);
            v2 += __shfl_down_sync(0xffffffffu, v2, o);
        }
        o1 = v1; o2 = v2;
    }
}

// Branchless closed-form nearest E8 root. All 240 roots have |r|^2=2, so
// nearest = argmax<residual,root>, computed analytically from root structure.
__device__ __forceinline__ int e8_nearest(const float r[8], float root_out[8]) {
    float a[8];
    unsigned smask = 0;   // sign bits, bit k
    unsigned rmask = 0;   // sign bits, bit (7-k)  (root-list enumeration order)
    #pragma unroll
    for (int k = 0; k < 8; k++) {
        unsigned sb = __float_as_uint(r[k]) >> 31;
        smask |= sb << k;
        rmask |= sb << (7 - k);
        a[k] = fabsf(r[k]);
    }

    // --- max (tree) + first index achieving it ---
    float m01 = fmaxf(a[0], a[1]), m23 = fmaxf(a[2], a[3]);
    float m45 = fmaxf(a[4], a[5]), m67 = fmaxf(a[6], a[7]);
    float a1 = fmaxf(fmaxf(m01, m23), fmaxf(m45, m67));
    unsigned em = 0;
    #pragma unroll
    for (int k = 0; k < 8; k++) em |= (a[k] == a1) ? (1u << k) : 0u;
    int i1 = __ffs(em) - 1;

    // --- second max: exclude i1 (a[] >= 0, so -1 acts as -inf) ---
    float b0 = (i1 == 0) ? -1.0f : a[0], b1 = (i1 == 1) ? -1.0f : a[1];
    float b2 = (i1 == 2) ? -1.0f : a[2], b3 = (i1 == 3) ? -1.0f : a[3];
    float b4 = (i1 == 4) ? -1.0f : a[4], b5 = (i1 == 5) ? -1.0f : a[5];
    float b6 = (i1 == 6) ? -1.0f : a[6], b7 = (i1 == 7) ? -1.0f : a[7];
    float a2 = fmaxf(fmaxf(fmaxf(b0, b1), fmaxf(b2, b3)),
                     fmaxf(fmaxf(b4, b5), fmaxf(b6, b7)));
    unsigned em2 = 0;
    em2 |= (b0 == a2) ? 1u : 0u;        em2 |= (b1 == a2) ? 2u : 0u;
    em2 |= (b2 == a2) ? 4u : 0u;        em2 |= (b3 == a2) ? 8u : 0u;
    em2 |= (b4 == a2) ? 16u : 0u;       em2 |= (b5 == a2) ? 32u : 0u;
    em2 |= (b6 == a2) ? 64u : 0u;       em2 |= (b7 == a2) ? 128u : 0u;
    int i2 = __ffs(em2) - 1;

    // --- sum, min + first index achieving it, parity ---
    float s = ((a[0] + a[1]) + (a[2] + a[3])) + ((a[4] + a[5]) + (a[6] + a[7]));
    float n01 = fminf(a[0], a[1]), n23 = fminf(a[2], a[3]);
    float n45 = fminf(a[4], a[5]), n67 = fminf(a[6], a[7]);
    float amin = fminf(fminf(n01, n23), fminf(n45, n67));
    unsigned nm = 0;
    #pragma unroll
    for (int k = 0; k < 8; k++) nm |= (a[k] == amin) ? (1u << k) : 0u;
    int imin = __ffs(nm) - 1;

    unsigned par = __popc(smask) & 1u;

    float pairDot = a1 + a2;
    float halfDot = 0.5f * s - (par ? amin : 0.0f);
    bool usePair = pairDot >= halfDot;

    // --- pair index: i<j among {i1,i2}; sign bits from smask ---
    int i = min(i1, i2), j = max(i1, i2);
    int pidx = i * 7 - ((i * (i - 1)) >> 1) + (j - i - 1);
    unsigned si = (smask >> i) & 1u, sj = (smask >> j) & 1u;
    int idxPair = 4 * pidx + 2 * (int)si + (int)sj;

    // --- half index: flip sign of min component if parity odd ---
    unsigned hv = rmask ^ (par << (7 - imin));
    int idxHalf = 112 + (int)(hv >> 1);

    #pragma unroll
    for (int k = 0; k < 8; k++) {
        float sgn = ((smask >> k) & 1u) ? -1.0f : 1.0f;
        float pairRoot = ((k == i1) | (k == i2)) ? sgn : 0.0f;
        float halfRoot = ((hv >> (7 - k)) & 1u) ? -0.5f : 0.5f;
        root_out[k] = usePair ? pairRoot : halfRoot;
    }
    return usePair ? idxPair : idxHalf;
}

__device__ __forceinline__ void qmul(const float q[4], const float p[4], float o[4]) {
    o[0] = q[0]*p[0] - q[1]*p[1] - q[2]*p[2] - q[3]*p[3];
    o[1] = q[0]*p[1] + q[1]*p[0] + q[2]*p[3] - q[3]*p[2];
    o[2] = q[0]*p[2] - q[1]*p[3] + q[2]*p[0] + q[3]*p[1];
    o[3] = q[0]*p[3] + q[1]*p[2] - q[2]*p[1] + q[3]*p[0];
}

// Shared body; FULL=true -> no bounds predicates (block entirely in range).
template <bool FULL>
__device__ __forceinline__ void fused_body(
        const float* __restrict__ states,
        float* __restrict__ out,
        const int* __restrict__ li,
        const int* __restrict__ lj,
        const int* __restrict__ lk,
        float* __restrict__ prod_out,
        float* __restrict__ align_out,
        int nrows, size_t off_idx, int rem,
        float* sq, float* prs, float& qe, float& fsv) {
    int tid = threadIdx.x;
    int row = blockIdx.x * TPB + tid;
    int b_local = tid / 7;
    int sub     = tid - b_local * 7;

    // ---------------- Phase 1: residual E8 quantization ----------------
    if (FULL || tid < rem) {
        float x[8];
        const float4* p = reinterpret_cast<const float4*>(states + (size_t)row * 8);
        float4 v0 = p[0], v1 = p[1];
        x[0] = v0.x; x[1] = v0.y; x[2] = v0.z; x[3] = v0.w;
        x[4] = v1.x; x[5] = v1.y; x[6] = v1.z; x[7] = v1.w;

        float res[8], root[8], qsum[8];
        #pragma unroll
        for (int k = 0; k < 8; k++) res[k] = x[k];

        int idx0 = e8_nearest(res, root);
        #pragma unroll
        for (int k = 0; k < 8; k++) { qsum[k] = root[k]; res[k] = x[k] - qsum[k]; }

        int idx1 = e8_nearest(res, root);
        #pragma unroll
        for (int k = 0; k < 8; k++) {
            qsum[k] += root[k];
            float d = x[k] - qsum[k];
            qe += d * d;
        }

        // smem layout is linear: row tid -> floats [tid*8, tid*8+8)
        float4* sp = reinterpret_cast<float4*>(sq + tid * 8);
        sp[0] = make_float4(qsum[0], qsum[1], qsum[2], qsum[3]);
        sp[1] = make_float4(qsum[4], qsum[5], qsum[6], qsum[7]);

        out[off_idx + row]                 = (float)idx0;
        out[off_idx + (size_t)nrows + row] = (float)idx1;
    }
    __syncthreads();

    // ------- Coalesced q writeout: smem is linear == global layout -------
    {
        size_t base_f = (size_t)blockIdx.x * TPB * 8;
        float4* qout = reinterpret_cast<float4*>(out + base_f);
        const float4* sq4 = reinterpret_cast<const float4*>(sq);
        if (FULL || (tid * 4) < rem * 8)
            qout[tid] = sq4[tid];
        if (FULL || ((tid + TPB) * 4) < rem * 8)
            qout[tid + TPB] = sq4[tid + TPB];
    }

    // ---------------- Phase 2: Fano octonion alignment (from smem) ------
    if (FULL || tid < rem) {
        int hi = __ldg(li + sub), hj = __ldg(lj + sub), hk = __ldg(lk + sub);
        const float* base = sq + b_local * SQ_STRIDE;
        const float4* av4 = reinterpret_cast<const float4*>(base + hi * 8);
        const float4* bv4 = reinterpret_cast<const float4*>(base + hj * 8);
        const float4* cv4 = reinterpret_cast<const float4*>(base + hk * 8);
        float4 aqv = av4[0], bqv = av4[1];
        float4 cqv = bv4[0], dqv = bv4[1];
        float4 cl  = cv4[0], ch  = cv4[1];

        float aq[4] = {aqv.x, aqv.y, aqv.z, aqv.w};
        float bq[4] = {bqv.x, bqv.y, bqv.z, bqv.w};
        float cq[4] = {cqv.x, cqv.y, cqv.z, cqv.w};
        float dq[4] = {dqv.x, dqv.y, dqv.z, dqv.w};
        float dconj[4] = {dq[0], -dq[1], -dq[2], -dq[3]};
        float cconj[4] = {cq[0], -cq[1], -cq[2], -cq[3]};
        float cv[8] = {cl.x, cl.y, cl.z, cl.w, ch.x, ch.y, ch.z, ch.w};

        float t1[4], t2[4], t3[4], t4[4], pr[8];
        qmul(aq, cq, t1);
        qmul(dconj, bq, t2);
        qmul(dq, aq, t3);
        qmul(bq, cconj, t4);

        float dot = 0.0f, np2 = 0.0f, nc2 = 0.0f;
        #pragma unroll
        for (int k = 0; k < 4; k++) {
            float plo = t1[k] - t2[k];
            float phi = t3[k] + t4[k];
            float clo = cv[k], chi = cv[4 + k];
            dot += plo * clo + phi * chi;
            np2 += plo * plo + phi * phi;
            nc2 += clo * clo + chi * chi;
            pr[k]     = plo;
            pr[4 + k] = phi;
        }
        // staged products: linear layout, 2x STS.128
        float4* pw = reinterpret_cast<float4*>(prs + tid * 8);
        pw[0] = make_float4(pr[0], pr[1], pr[2], pr[3]);
        pw[1] = make_float4(pr[4], pr[5], pr[6], pr[7]);

        float align = dot * rsqrtf(fmaxf(np2 * nc2, 1e-16f));
        align_out[(size_t)blockIdx.x * TPB + tid] = align;

        float ac = fminf(fmaxf(align, -1.0f), 1.0f);
        fsv = 1.0f - ac;
    }
    __syncthreads();

    // ------- Coalesced products writeout (linear smem, dense global) -----
    {
        size_t base_f = (size_t)blockIdx.x * TPB * 8;
        float* gp = prod_out + base_f + tid;
        #pragma unroll
        for (int jj = 0; jj < 8; jj++) {
            if (FULL || (tid + jj * TPB) < rem * 8)
                gp[jj * TPB] = prs[tid + jj * TPB];
        }
    }
}

__global__ void __launch_bounds__(TPB, 7)
fused_kernel(const float* __restrict__ states,
             float* __restrict__ out,
             const int* __restrict__ li,
             const int* __restrict__ lj,
             const int* __restrict__ lk,
             float* __restrict__ prod_out,
             float* __restrict__ align_out,
             float* __restrict__ qerr_out,
             float* __restrict__ fano_out,
             int nrows, size_t off_idx,
             double inv_nq, double inv_nf,
             unsigned nblocks) {
    __shared__ float sq[BPB * SQ_STRIDE];    // 7168 B
    __shared__ float prs[TPB * PR_STRIDE];   // 7168 B

    int rem = nrows - blockIdx.x * TPB;
    float qe = 0.0f, fsv = 0.0f;

    if (rem >= TPB) {
        fused_body<true>(states, out, li, lj, lk, prod_out, align_out,
                         nrows, off_idx, rem, sq, prs, qe, fsv);
    } else {
        fused_body<false>(states, out, li, lj, lk, prod_out, align_out,
                          nrows, off_idx, rem, sq, prs, qe, fsv);
    }

    // ---------------- Reduction + last-block finalize ----------------
    float bq_, bf_;
    blockReduce2F(qe, fsv, bq_, bf_);

    __shared__ bool amLast;
    if (threadIdx.x == 0) {
        atomicAdd(&g_qerr_sum, (double)bq_);
        atomicAdd(&g_fano_sum, (double)bf_);
        __threadfence();
        unsigned done = atomicAdd(&g_count, 1u);
        amLast = (done == nblocks - 1);
    }
    __syncthreads();
    if (amLast && threadIdx.x == 0) {
        double tq = *((volatile double*)&g_qerr_sum);
        double tf = *((volatile double*)&g_fano_sum);
        *qerr_out = (float)(tq * inv_nq);
        double fl = tf * inv_nf * 0.5;
        if (fl < 0.0) fl = 0.0;
        if (fl > 1.0) fl = 1.0;
        *fano_out = (float)fl;
        g_qerr_sum = 0.0;
        g_fano_sum = 0.0;
        g_count = 0;
    }
}

extern "C" void kernel_launch(void* const* d_in, const int* in_sizes, int n_in,
                              void* d_out, int out_size) {
    const float* states = (const float*)d_in[0];
    // d_in[1] = roots (structure known analytically; not needed)
    const int* li = (const int*)d_in[2];
    const int* lj = (const int*)d_in[3];
    const int* lk = (const int*)d_in[4];

    int B = in_sizes[0] / (HH * 8);      // 65536
    int nrows = B * HH;                  // 458752 = 224 * 2048

    float* out = (float*)d_out;
    size_t off_idx   = (size_t)nrows * 8;                 // quantized_ste
    size_t off_qerr  = off_idx + 2 * (size_t)nrows;       // indices (2, B, H)
    size_t off_prod  = off_qerr + 1;                      // q_err scalar
    size_t off_align = off_prod + (size_t)B * LL * 8;     // products (B, L, 8)
    size_t off_fano  = off_align + (size_t)B * LL;        // alignments (B, L)

    unsigned nblocks = (unsigned)((nrows + TPB - 1) / TPB);   // 2048

    fused_kernel<<<nblocks, TPB>>>(states, out, li, lj, lk,
                                   out + off_prod, out + off_align,
                                   out + off_qerr, out + off_fano,
                                   nrows, off_idx,
                                   1.0 / ((double)nrows * 8.0),
                                   1.0 / ((double)B * (double)LL),
                                   nblocks);
}